// round 10
// baseline (speedup 1.0000x reference)
#include <cuda_runtime.h>
#include <cstddef>

// 2-layer tanh RNN (B=2048,T=512,I=8,H=64)+FC.
// R9: layer-fused phases (h0(t) + h1(t-1)), one barrier/phase, inline x-term,
// 7-shuffle slot-permuted reduction, conflict-free rotated h layout,
// weights in registers, grid 128 = 1 wave.

#define TT 512
typedef unsigned long long u64;

static __device__ __forceinline__ void fma2(u64& a, u64 u, u64 v) {
    asm("fma.rn.f32x2 %0, %1, %2, %0;" : "+l"(a) : "l"(u), "l"(v));
}
static __device__ __forceinline__ u64 mul2(u64 u, u64 v) {
    u64 r; asm("mul.rn.f32x2 %0, %1, %2;" : "=l"(r) : "l"(u), "l"(v)); return r;
}
static __device__ __forceinline__ u64 add2(u64 a, u64 b) {
    u64 r; asm("add.rn.f32x2 %0, %1, %2;" : "=l"(r) : "l"(a), "l"(b)); return r;
}
static __device__ __forceinline__ u64 pack2(float a, float b) {
    u64 r; asm("mov.b64 %0, {%1, %2};" : "=l"(r) : "f"(a), "f"(b)); return r;
}
static __device__ __forceinline__ void unpack2(u64 v, float& a, float& b) {
    asm("mov.b64 {%0, %1}, %2;" : "=f"(a), "=f"(b) : "l"(v));
}
static __device__ __forceinline__ u64 dup2(float a) {
    u64 r; asm("mov.b64 %0, {%1, %1};" : "=l"(r) : "f"(a)); return r;
}
static __device__ __forceinline__ float ftanh(float s) {
    const float e = __expf(2.0f * s);
    return 1.0f - __fdividef(2.0f, e + 1.0f);
}
static __device__ __forceinline__ u64 shx(u64 v, int m) {
    return __shfl_xor_sync(0xffffffffu, v, m, 32);
}
// fold two row-half accs into one packed pair value
static __device__ __forceinline__ u64 foldp(u64 a, u64 b) {
    float l0, m0, l1, m1;
    unpack2(a, l0, m0); unpack2(b, l1, m1);
    return pack2(l0 + m0, l1 + m1);
}

__global__ void __launch_bounds__(512, 1)
rnn_main(const float* __restrict__ x,
         const float* __restrict__ Wih0, const float* __restrict__ Whh0,
         const float* __restrict__ bi0,  const float* __restrict__ bh0,
         const float* __restrict__ Wih1, const float* __restrict__ Whh1,
         const float* __restrict__ bi1,  const float* __restrict__ bh1,
         const float* __restrict__ fcw,  const float* __restrict__ fcb,
         float* __restrict__ out)
{
    __shared__ __align__(16) float h0s[2][16 * 64];
    __shared__ __align__(16) float h1s[2][16 * 64];

    const int tid  = threadIdx.x;
    const int lane = tid & 31;
    const int w    = tid >> 5;               // rows j0..j0+3
    const int b    = lane & 3;
    const int kg   = lane >> 2;              // k in [8kg, 8kg+8)
    const int s    = kg & 1;                 // owned row-pair
    const int p2   = (((kg >> 1) & 1) << 1) | ((kg >> 2) & 1);  // owned chunk
    const int j0   = w * 4;
    const int g    = (b & 1) | ((b & 2) << 1);

    for (int i = tid; i < 16 * 64; i += 512) {
        h0s[1][i] = 0.f; h1s[0][i] = 0.f; h1s[1][i] = 0.f;
    }

    // Per-chunk-slot offsets (chunk(slot c) = c ^ p2; batch = chunk*4+b)
    int ofA[4], ofB[4], xof[4];
#pragma unroll
    for (int c = 0; c < 4; c++) {
        const int B = (c ^ p2) * 4 + b;
        ofA[c] = B * 64 + (((2 * kg     + g) & 15) << 2);
        ofB[c] = B * 64 + (((2 * kg + 1 + g) & 15) << 2);
        xof[c] = (blockIdx.x * 16 + B) * (TT * 8) + kg;
    }
    const int sto = (p2 * 4 + b) * 64 + (((w + g) & 15) << 2) + 2 * s;

    // Weights in registers; row slot q covers physical row-pair (q^s).
    u64 wa[2][2][4], wb[2][2][4], wc[2][2][4], wxp[2];
#pragma unroll
    for (int q = 0; q < 2; q++) {
        const int jA = j0 + 2 * (q ^ s);
#pragma unroll
        for (int h = 0; h < 2; h++) {
            const int base = ((jA + h) * 64 + kg * 8) >> 1;
#pragma unroll
            for (int kk = 0; kk < 4; kk++) {
                wa[q][h][kk] = reinterpret_cast<const u64*>(Whh0)[base + kk];
                wb[q][h][kk] = reinterpret_cast<const u64*>(Wih1)[base + kk];
                wc[q][h][kk] = reinterpret_cast<const u64*>(Whh1)[base + kk];
            }
        }
        wxp[q] = pack2(Wih0[jA * 8 + kg], Wih0[(jA + 1) * 8 + kg]);
    }
    const u64 bz0 = pack2(bi0[j0+2*s] + bh0[j0+2*s], bi0[j0+2*s+1] + bh0[j0+2*s+1]);
    const u64 bz1 = pack2(bi1[j0+2*s] + bh1[j0+2*s], bi1[j0+2*s+1] + bh1[j0+2*s+1]);

    float xv[4];
#pragma unroll
    for (int c = 0; c < 4; c++) xv[c] = x[xof[c]];   // t = 0

    __syncthreads();

#pragma unroll 1
    for (int t = 0; t < TT; t++) {
        const int p = t & 1, pq = p ^ 1;

        // prefetch x for t+1 (clamped; dead value at t=TT-1)
        const int tn = (t + 1 < TT) ? (t + 1) : t;
        float xn[4];
#pragma unroll
        for (int c = 0; c < 4; c++) xn[c] = x[xof[c] + tn * 8];

        u64 v0[4], v1[4];
#pragma unroll
        for (int c = 0; c < 4; c++) {
            const u64* qa0 = reinterpret_cast<const u64*>(&h0s[pq][ofA[c]]);
            const u64* qb0 = reinterpret_cast<const u64*>(&h0s[pq][ofB[c]]);
            const u64 u0 = qa0[0], u1 = qa0[1], u2 = qb0[0], u3 = qb0[1];
            u64 a0[2][2], a1[2][2];
#pragma unroll
            for (int q = 0; q < 2; q++)
#pragma unroll
                for (int h = 0; h < 2; h++) {
                    a0[q][h] = mul2(wa[q][h][0], u0);
                    fma2(a0[q][h], wa[q][h][1], u1);
                    fma2(a0[q][h], wa[q][h][2], u2);
                    fma2(a0[q][h], wa[q][h][3], u3);
                    a1[q][h] = mul2(wb[q][h][0], u0);
                    fma2(a1[q][h], wb[q][h][1], u1);
                    fma2(a1[q][h], wb[q][h][2], u2);
                    fma2(a1[q][h], wb[q][h][3], u3);
                }
            const u64* qa1 = reinterpret_cast<const u64*>(&h1s[pq][ofA[c]]);
            const u64* qb1 = reinterpret_cast<const u64*>(&h1s[pq][ofB[c]]);
            const u64 z0 = qa1[0], z1 = qa1[1], z2 = qb1[0], z3 = qb1[1];
#pragma unroll
            for (int q = 0; q < 2; q++)
#pragma unroll
                for (int h = 0; h < 2; h++) {
                    fma2(a1[q][h], wc[q][h][0], z0);
                    fma2(a1[q][h], wc[q][h][1], z1);
                    fma2(a1[q][h], wc[q][h][2], z2);
                    fma2(a1[q][h], wc[q][h][3], z3);
                }
            // fold + x-term, then round A (xor4: merges row-pair slots)
            u64 p00 = foldp(a0[0][0], a0[0][1]);
            u64 p01 = foldp(a0[1][0], a0[1][1]);
            const u64 xd = dup2(xv[c]);
            fma2(p00, wxp[0], xd);
            fma2(p01, wxp[1], xd);
            v0[c] = add2(p00, shx(p01, 4));
            u64 p10 = foldp(a1[0][0], a1[0][1]);
            u64 p11 = foldp(a1[1][0], a1[1][1]);
            v1[c] = add2(p10, shx(p11, 4));
        }
        // round B (xor8: chunk bit1), round C (xor16: chunk bit0)
        v0[0] = add2(v0[0], shx(v0[2], 8));
        v0[1] = add2(v0[1], shx(v0[3], 8));
        v1[0] = add2(v1[0], shx(v1[2], 8));
        v1[1] = add2(v1[1], shx(v1[3], 8));
        u64 r0 = add2(v0[0], shx(v0[1], 16));
        u64 r1 = add2(v1[0], shx(v1[1], 16));

        {
            r0 = add2(r0, bz0);
            float f0, f1;
            unpack2(r0, f0, f1);
            *reinterpret_cast<u64*>(&h0s[p][sto]) = pack2(ftanh(f0), ftanh(f1));
        }
        if (t > 0) {                       // h1(-1) = 0: skip phase-0 store
            r1 = add2(r1, bz1);
            float f0, f1;
            unpack2(r1, f0, f1);
            *reinterpret_cast<u64*>(&h1s[p][sto]) = pack2(ftanh(f0), ftanh(f1));
        }
#pragma unroll
        for (int c = 0; c < 4; c++) xv[c] = xn[c];
        __syncthreads();                   // the ONE barrier per phase
    }

    // Epilogue: h1(TT-1) from h0(TT-1)=h0s[1], h1(TT-2)=h1s[1] -> h1s[0]
    {
        u64 v1[4];
#pragma unroll
        for (int c = 0; c < 4; c++) {
            const u64* qa0 = reinterpret_cast<const u64*>(&h0s[1][ofA[c]]);
            const u64* qb0 = reinterpret_cast<const u64*>(&h0s[1][ofB[c]]);
            const u64 u0 = qa0[0], u1 = qa0[1], u2 = qb0[0], u3 = qb0[1];
            u64 a1[2][2];
#pragma unroll
            for (int q = 0; q < 2; q++)
#pragma unroll
                for (int h = 0; h < 2; h++) {
                    a1[q][h] = mul2(wb[q][h][0], u0);
                    fma2(a1[q][h], wb[q][h][1], u1);
                    fma2(a1[q][h], wb[q][h][2], u2);
                    fma2(a1[q][h], wb[q][h][3], u3);
                }
            const u64* qa1 = reinterpret_cast<const u64*>(&h1s[1][ofA[c]]);
            const u64* qb1 = reinterpret_cast<const u64*>(&h1s[1][ofB[c]]);
            const u64 z0 = qa1[0], z1 = qa1[1], z2 = qb1[0], z3 = qb1[1];
#pragma unroll
            for (int q = 0; q < 2; q++)
#pragma unroll
                for (int h = 0; h < 2; h++) {
                    fma2(a1[q][h], wc[q][h][0], z0);
                    fma2(a1[q][h], wc[q][h][1], z1);
                    fma2(a1[q][h], wc[q][h][2], z2);
                    fma2(a1[q][h], wc[q][h][3], z3);
                }
            u64 p10 = foldp(a1[0][0], a1[0][1]);
            u64 p11 = foldp(a1[1][0], a1[1][1]);
            v1[c] = add2(p10, shx(p11, 4));
        }
        v1[0] = add2(v1[0], shx(v1[2], 8));
        v1[1] = add2(v1[1], shx(v1[3], 8));
        u64 r1 = add2(v1[0], shx(v1[1], 16));
        r1 = add2(r1, bz1);
        float f0, f1;
        unpack2(r1, f0, f1);
        *reinterpret_cast<u64*>(&h1s[0][sto]) = pack2(ftanh(f0), ftanh(f1));
    }
    __syncthreads();

    // FC: out[b] = h1(T-1) . fcw + fcb   (h1(T-1) in h1s[0])
    if (tid < 16) {
        const int gg = (tid & 1) | ((tid & 2) << 1);
        float sum = fcb[0];
#pragma unroll
        for (int q = 0; q < 16; q++) {
            const float4 hv = *reinterpret_cast<const float4*>(
                &h1s[0][tid * 64 + (((q + gg) & 15) << 2)]);
            const float4 wv = reinterpret_cast<const float4*>(fcw)[q];
            sum += hv.x * wv.x + hv.y * wv.y + hv.z * wv.z + hv.w * wv.w;
        }
        out[blockIdx.x * 16 + tid] = sum;
    }
}

extern "C" void kernel_launch(void* const* d_in, const int* in_sizes, int n_in,
                              void* d_out, int out_size)
{
    // Inputs: x, W_ih0, W_hh0, b_ih0, b_hh0, W_ih1, W_hh1, b_ih1, b_hh1, fc_w, fc_b
    (void)in_sizes; (void)n_in; (void)out_size;
    rnn_main<<<128, 512>>>(
        (const float*)d_in[0],
        (const float*)d_in[1], (const float*)d_in[2],
        (const float*)d_in[3], (const float*)d_in[4],
        (const float*)d_in[5], (const float*)d_in[6],
        (const float*)d_in[7], (const float*)d_in[8],
        (const float*)d_in[9], (const float*)d_in[10],
        (float*)d_out);
}

// round 11
// speedup vs baseline: 1.7633x; 1.7633x over previous
#include <cuda_runtime.h>
#include <cstddef>

// 2-layer tanh RNN (B=2048,T=512,I=8,H=64)+FC.
// R10 = R7 trunk (weight-stationary registers, k-split-8, conflict-free
// rotated h layout, 1 barrier/step, grid 128 = 1 wave) + R9's slot-permuted
// 7-shuffle reduction per layer (no keep-SELs). NO layer fusion (reg cap).

#define TT 512
typedef unsigned long long u64;

static __device__ __forceinline__ void fma2(u64& a, u64 u, u64 v) {
    asm("fma.rn.f32x2 %0, %1, %2, %0;" : "+l"(a) : "l"(u), "l"(v));
}
static __device__ __forceinline__ u64 mul2(u64 u, u64 v) {
    u64 r; asm("mul.rn.f32x2 %0, %1, %2;" : "=l"(r) : "l"(u), "l"(v)); return r;
}
static __device__ __forceinline__ u64 add2(u64 a, u64 b) {
    u64 r; asm("add.rn.f32x2 %0, %1, %2;" : "=l"(r) : "l"(a), "l"(b)); return r;
}
static __device__ __forceinline__ u64 pack2(float a, float b) {
    u64 r; asm("mov.b64 %0, {%1, %2};" : "=l"(r) : "f"(a), "f"(b)); return r;
}
static __device__ __forceinline__ void unpack2(u64 v, float& a, float& b) {
    asm("mov.b64 {%0, %1}, %2;" : "=f"(a), "=f"(b) : "l"(v));
}
static __device__ __forceinline__ u64 dup2(float a) {
    u64 r; asm("mov.b64 %0, {%1, %1};" : "=l"(r) : "f"(a)); return r;
}
static __device__ __forceinline__ float ftanh(float s) {
    const float e = __expf(2.0f * s);
    return 1.0f - __fdividef(2.0f, e + 1.0f);
}
static __device__ __forceinline__ u64 shx(u64 v, int m) {
    return __shfl_xor_sync(0xffffffffu, v, m, 32);
}
static __device__ __forceinline__ u64 foldp(u64 a, u64 b) {
    float l0, m0, l1, m1;
    unpack2(a, l0, m0); unpack2(b, l1, m1);
    return pack2(l0 + m0, l1 + m1);   // mov.b64 splits are reg-aliases: 2 FADDs
}

__global__ void __launch_bounds__(512, 1)
rnn_main(const float* __restrict__ x,
         const float* __restrict__ Wih0, const float* __restrict__ Whh0,
         const float* __restrict__ bi0,  const float* __restrict__ bh0,
         const float* __restrict__ Wih1, const float* __restrict__ Whh1,
         const float* __restrict__ bi1,  const float* __restrict__ bh1,
         const float* __restrict__ fcw,  const float* __restrict__ fcb,
         float* __restrict__ out)
{
    __shared__ __align__(16) float h0s[2][16 * 64];
    __shared__ __align__(16) float h1s[2][16 * 64];

    const int tid  = threadIdx.x;
    const int lane = tid & 31;
    const int w    = tid >> 5;               // rows j0..j0+3
    const int b    = lane & 3;
    const int kg   = lane >> 2;              // k in [8kg, 8kg+8)
    const int s    = kg & 1;                 // owned row-pair
    const int p2   = (((kg >> 1) & 1) << 1) | ((kg >> 2) & 1);  // owned chunk
    const int j0   = w * 4;
    const int g    = (b & 1) | ((b & 2) << 1);

    for (int i = tid; i < 16 * 64; i += 512) { h0s[1][i] = 0.f; h1s[1][i] = 0.f; }

    // Per-chunk-slot offsets: chunk(slot c) = c ^ p2; batch = chunk*4 + b.
    int ofA[4], ofB[4], xof[4];
#pragma unroll
    for (int c = 0; c < 4; c++) {
        const int B = (c ^ p2) * 4 + b;
        ofA[c] = B * 64 + (((2 * kg     + g) & 15) << 2);
        ofB[c] = B * 64 + (((2 * kg + 1 + g) & 15) << 2);
        xof[c] = (blockIdx.x * 16 + B) * (TT * 8) + kg;
    }
    const int sto = (p2 * 4 + b) * 64 + (((w + g) & 15) << 2) + 2 * s;

    // Weights in registers; row slot q covers physical row-pair (q^s).
    u64 wa[2][2][4], wb[2][2][4], wc[2][2][4], wxp[2];
#pragma unroll
    for (int q = 0; q < 2; q++) {
        const int jA = j0 + 2 * (q ^ s);
#pragma unroll
        for (int h = 0; h < 2; h++) {
            const int base = ((jA + h) * 64 + kg * 8) >> 1;
#pragma unroll
            for (int kk = 0; kk < 4; kk++) {
                wa[q][h][kk] = reinterpret_cast<const u64*>(Whh0)[base + kk];
                wb[q][h][kk] = reinterpret_cast<const u64*>(Wih1)[base + kk];
                wc[q][h][kk] = reinterpret_cast<const u64*>(Whh1)[base + kk];
            }
        }
        wxp[q] = pack2(Wih0[jA * 8 + kg], Wih0[(jA + 1) * 8 + kg]);
    }
    const u64 bz0 = pack2(bi0[j0+2*s] + bh0[j0+2*s], bi0[j0+2*s+1] + bh0[j0+2*s+1]);
    const u64 bz1 = pack2(bi1[j0+2*s] + bh1[j0+2*s], bi1[j0+2*s+1] + bh1[j0+2*s+1]);

    __syncthreads();

#pragma unroll 1
    for (int t = 0; t < TT; t++) {
        const int p = t & 1, pq = p ^ 1;

        // ---------------- layer 0: Whh0 @ h0_prev + Wih0 @ x ----------------
        u64 vv[4];
#pragma unroll
        for (int c = 0; c < 4; c++) {
            const u64* qa = reinterpret_cast<const u64*>(&h0s[pq][ofA[c]]);
            const u64* qb = reinterpret_cast<const u64*>(&h0s[pq][ofB[c]]);
            const u64 u0 = qa[0], u1 = qa[1], u2 = qb[0], u3 = qb[1];
            u64 a[2][2];
#pragma unroll
            for (int q = 0; q < 2; q++)
#pragma unroll
                for (int h = 0; h < 2; h++) {
                    a[q][h] = mul2(wa[q][h][0], u0);
                    fma2(a[q][h], wa[q][h][1], u1);
                    fma2(a[q][h], wa[q][h][2], u2);
                    fma2(a[q][h], wa[q][h][3], u3);
                }
            u64 p0 = foldp(a[0][0], a[0][1]);
            u64 p1 = foldp(a[1][0], a[1][1]);
            const u64 xd = dup2(x[xof[c] + t * 8]);
            fma2(p0, wxp[0], xd);
            fma2(p1, wxp[1], xd);
            vv[c] = add2(p0, shx(p1, 4));          // round A
        }
        vv[0] = add2(vv[0], shx(vv[2], 8));        // round B
        vv[1] = add2(vv[1], shx(vv[3], 8));
        {
            u64 r0 = add2(vv[0], shx(vv[1], 16));  // round C
            r0 = add2(r0, bz0);
            float f0, f1;
            unpack2(r0, f0, f1);
            *reinterpret_cast<u64*>(&h0s[p][sto]) = pack2(ftanh(f0), ftanh(f1));
        }
        __syncthreads();                           // the ONE barrier per step

        // ---------- layer 1: Wih1 @ h0_new + Whh1 @ h1_prev ----------
#pragma unroll
        for (int c = 0; c < 4; c++) {
            const u64* qa0 = reinterpret_cast<const u64*>(&h0s[p][ofA[c]]);
            const u64* qb0 = reinterpret_cast<const u64*>(&h0s[p][ofB[c]]);
            const u64 u0 = qa0[0], u1 = qa0[1], u2 = qb0[0], u3 = qb0[1];
            u64 a[2][2];
#pragma unroll
            for (int q = 0; q < 2; q++)
#pragma unroll
                for (int h = 0; h < 2; h++) {
                    a[q][h] = mul2(wb[q][h][0], u0);
                    fma2(a[q][h], wb[q][h][1], u1);
                    fma2(a[q][h], wb[q][h][2], u2);
                    fma2(a[q][h], wb[q][h][3], u3);
                }
            const u64* qa1 = reinterpret_cast<const u64*>(&h1s[pq][ofA[c]]);
            const u64* qb1 = reinterpret_cast<const u64*>(&h1s[pq][ofB[c]]);
            const u64 z0 = qa1[0], z1 = qa1[1], z2 = qb1[0], z3 = qb1[1];
#pragma unroll
            for (int q = 0; q < 2; q++)
#pragma unroll
                for (int h = 0; h < 2; h++) {
                    fma2(a[q][h], wc[q][h][0], z0);
                    fma2(a[q][h], wc[q][h][1], z1);
                    fma2(a[q][h], wc[q][h][2], z2);
                    fma2(a[q][h], wc[q][h][3], z3);
                }
            u64 p0 = foldp(a[0][0], a[0][1]);
            u64 p1 = foldp(a[1][0], a[1][1]);
            vv[c] = add2(p0, shx(p1, 4));          // round A
        }
        vv[0] = add2(vv[0], shx(vv[2], 8));        // round B
        vv[1] = add2(vv[1], shx(vv[3], 8));
        {
            u64 r1 = add2(vv[0], shx(vv[1], 16));  // round C
            r1 = add2(r1, bz1);
            float f0, f1;
            unpack2(r1, f0, f1);
            *reinterpret_cast<u64*>(&h1s[p][sto]) = pack2(ftanh(f0), ftanh(f1));
        }
        // no trailing barrier: next step's mid barrier orders h1 writes/reads
    }

    __syncthreads();

    // FC: out[b] = h1(T-1) . fcw + fcb ; final parity = (TT-1)&1 = 1
    if (tid < 16) {
        const int gg = (tid & 1) | ((tid & 2) << 1);
        float sum = fcb[0];
#pragma unroll
        for (int q = 0; q < 16; q++) {
            const float4 hv = *reinterpret_cast<const float4*>(
                &h1s[1][tid * 64 + (((q + gg) & 15) << 2)]);
            const float4 wv = reinterpret_cast<const float4*>(fcw)[q];
            sum += hv.x * wv.x + hv.y * wv.y + hv.z * wv.z + hv.w * wv.w;
        }
        out[blockIdx.x * 16 + tid] = sum;
    }
}

extern "C" void kernel_launch(void* const* d_in, const int* in_sizes, int n_in,
                              void* d_out, int out_size)
{
    // Inputs: x, W_ih0, W_hh0, b_ih0, b_hh0, W_ih1, W_hh1, b_ih1, b_hh1, fc_w, fc_b
    (void)in_sizes; (void)n_in; (void)out_size;
    rnn_main<<<128, 512>>>(
        (const float*)d_in[0],
        (const float*)d_in[1], (const float*)d_in[2],
        (const float*)d_in[3], (const float*)d_in[4],
        (const float*)d_in[5], (const float*)d_in[6],
        (const float*)d_in[7], (const float*)d_in[8],
        (const float*)d_in[9], (const float*)d_in[10],
        (float*)d_out);
}